// round 3
// baseline (speedup 1.0000x reference)
#include <cuda_runtime.h>

#define NN 50000
#define NE 800000
#define KDIM 256

// ---------------- scratch (static device globals; no allocation) ----------------
__device__ float g_H1[(size_t)NN * 256];    // layer1 projected features
__device__ float g_h2s[(size_t)NN * 256];   // relu(conv1) * norm_src
__device__ float g_H2p[(size_t)NN * 128];   // layer2 projected features
__device__ int   g_deg_out[NN];
__device__ int   g_deg_in[NN];
__device__ float g_ns[NN];                  // norm_src = clip(deg_out,1)^-0.5
__device__ float g_nd[NN];                  // norm_dst = clip(deg_in,1)^-0.5
__device__ int   g_rowptr[NN + 1];
__device__ int   g_cursor[NN];
__device__ int   g_csrc[NE];                // CSR-by-dst: source node ids
__device__ int   g_is64;                    // 1 if src/dst are int64, 0 if int32

// ---------------- edge index accessor (dtype-robust) ----------------
__device__ __forceinline__ int edge_at(const void* p, int i, int is64) {
    if (is64) return (int)((const long long*)p)[i];
    return ((const int*)p)[i];
}

// detect int64 vs int32: if src is int64 with values < 2^31, every odd int32
// word (high half) is zero. For random int32 ids in [0,50000) the chance all
// 256 odd words are zero is ~0.
__global__ void k_detect(const int* __restrict__ src_as_i32) {
    if (threadIdx.x == 0) {
        int allzero = 1;
        for (int i = 0; i < 256; i++)
            if (src_as_i32[2 * i + 1] != 0) { allzero = 0; break; }
        g_is64 = allzero;
    }
}

// ---------------- graph prep ----------------
__global__ void k_zero() {
    int i = blockIdx.x * 256 + threadIdx.x;
    if (i < NN) { g_deg_out[i] = 0; g_deg_in[i] = 0; g_cursor[i] = 0; }
}

__global__ void k_degree(const void* __restrict__ src,
                         const void* __restrict__ dst) {
    int e = blockIdx.x * 256 + threadIdx.x;
    if (e < NE) {
        int is64 = g_is64;
        unsigned s = (unsigned)edge_at(src, e, is64);
        unsigned d = (unsigned)edge_at(dst, e, is64);
        if (s < NN) atomicAdd(&g_deg_out[s], 1);
        if (d < NN) atomicAdd(&g_deg_in[d], 1);
    }
}

__global__ void k_norm() {
    int i = blockIdx.x * 256 + threadIdx.x;
    if (i < NN) {
        int a = g_deg_out[i]; if (a < 1) a = 1;
        int b = g_deg_in[i];  if (b < 1) b = 1;
        g_ns[i] = rsqrtf((float)a);
        g_nd[i] = rsqrtf((float)b);
    }
}

// single-block exclusive scan of deg_in -> rowptr
__global__ void k_scan() {
    __shared__ int sh[1024];
    const int CH = (NN + 1023) / 1024;  // 49
    int tid = threadIdx.x;
    int st = tid * CH;
    int en = st + CH; if (en > NN) en = NN;
    int s = 0;
    for (int j = st; j < en; ++j) s += g_deg_in[j];
    sh[tid] = s;
    __syncthreads();
    for (int off = 1; off < 1024; off <<= 1) {
        int v = 0;
        if (tid >= off) v = sh[tid - off];
        __syncthreads();
        sh[tid] += v;
        __syncthreads();
    }
    int run = sh[tid] - s;  // exclusive prefix
    for (int j = st; j < en; ++j) { g_rowptr[j] = run; run += g_deg_in[j]; }
    if (tid == 1023) g_rowptr[NN] = sh[1023];
}

__global__ void k_csr(const void* __restrict__ src,
                      const void* __restrict__ dst) {
    int e = blockIdx.x * 256 + threadIdx.x;
    if (e < NE) {
        int is64 = g_is64;
        unsigned s = (unsigned)edge_at(src, e, is64);
        unsigned d = (unsigned)edge_at(dst, e, is64);
        if (s < NN && d < NN) {
            int pos = atomicAdd(&g_cursor[d], 1);
            int slot = g_rowptr[d] + pos;
            if (slot < NE) g_csrc[slot] = (int)s;
        }
    }
}

// ---------------- GEMM: C[M,Nt] = (A .* rowscale) @ B[256,Nt] ----------------
// BM=128, BN=128, BK=16, 256 threads, TM=TN=8
template <bool L1>
__global__ void __launch_bounds__(256) k_gemm(const float* __restrict__ Ain,
                                              const float* __restrict__ B) {
    constexpr int Nt = L1 ? 256 : 128;
    const float* A = L1 ? Ain : (const float*)g_h2s;
    float* C = L1 ? g_H1 : g_H2p;

    __shared__ __align__(16) float As[16][128];
    __shared__ __align__(16) float Bs[16][128];

    int brow = blockIdx.x * 128;
    int bcol = blockIdx.y * 128;
    int tid = threadIdx.x;
    int tx = tid & 15;
    int ty = tid >> 4;

    float acc[8][8];
#pragma unroll
    for (int i = 0; i < 8; i++)
#pragma unroll
        for (int j = 0; j < 8; j++) acc[i][j] = 0.f;

    for (int k0 = 0; k0 < KDIM; k0 += 16) {
        // load A tile 128x16 (transposed into As[k][m]), scaled by norm_src for layer 1
#pragma unroll
        for (int i = 0; i < 2; i++) {
            int idx = tid * 2 + i;          // 0..511
            int ar = idx >> 2;              // row within tile 0..127
            int ac = (idx & 3) * 4;         // col within tile 0,4,8,12
            int gr = brow + ar;
            float4 v = make_float4(0.f, 0.f, 0.f, 0.f);
            if (gr < NN) {
                v = *(const float4*)(A + (size_t)gr * KDIM + k0 + ac);
                if (L1) {
                    float s = g_ns[gr];
                    v.x *= s; v.y *= s; v.z *= s; v.w *= s;
                }
            }
            As[ac + 0][ar] = v.x;
            As[ac + 1][ar] = v.y;
            As[ac + 2][ar] = v.z;
            As[ac + 3][ar] = v.w;
        }
        // load B tile 16x128
#pragma unroll
        for (int i = 0; i < 2; i++) {
            int idx = tid * 2 + i;
            int br = idx >> 5;              // 0..15
            int bc = (idx & 31) * 4;        // 0..124
            *(float4*)&Bs[br][bc] =
                *(const float4*)(B + (size_t)(k0 + br) * Nt + bcol + bc);
        }
        __syncthreads();

#pragma unroll
        for (int k = 0; k < 16; k++) {
            float4 a0 = *(const float4*)&As[k][ty * 8];
            float4 a1 = *(const float4*)&As[k][ty * 8 + 4];
            float4 b0 = *(const float4*)&Bs[k][tx * 8];
            float4 b1 = *(const float4*)&Bs[k][tx * 8 + 4];
            float ra[8] = {a0.x, a0.y, a0.z, a0.w, a1.x, a1.y, a1.z, a1.w};
            float rb[8] = {b0.x, b0.y, b0.z, b0.w, b1.x, b1.y, b1.z, b1.w};
#pragma unroll
            for (int i = 0; i < 8; i++)
#pragma unroll
                for (int j = 0; j < 8; j++) acc[i][j] += ra[i] * rb[j];
        }
        __syncthreads();
    }

#pragma unroll
    for (int i = 0; i < 8; i++) {
        int gr = brow + ty * 8 + i;
        if (gr >= NN) continue;
#pragma unroll
        for (int j = 0; j < 8; j += 4) {
            float4 v = make_float4(acc[i][j], acc[i][j + 1], acc[i][j + 2], acc[i][j + 3]);
            *(float4*)(C + (size_t)gr * Nt + bcol + tx * 8 + j) = v;
        }
    }
}

// ---------------- aggregation (CSR gather-sum, no float atomics) ----------------
// layer 1: h2s[node] = relu(sum_{s in in(node)} H1[s] * nd + b1) * ns
__global__ void k_agg1(const float* __restrict__ b1) {
    int node = blockIdx.x * blockDim.y + threadIdx.y;
    if (node >= NN) return;
    int f = threadIdx.x;  // 0..63 float4 lanes
    const float4* H = (const float4*)g_H1;
    int beg = g_rowptr[node], end = g_rowptr[node + 1];

    float4 a = make_float4(0.f, 0.f, 0.f, 0.f);
    float4 b = make_float4(0.f, 0.f, 0.f, 0.f);
    int e = beg;
    for (; e + 2 <= end; e += 2) {
        int s0 = g_csrc[e], s1 = g_csrc[e + 1];
        float4 v0 = H[(size_t)s0 * 64 + f];
        float4 v1 = H[(size_t)s1 * 64 + f];
        a.x += v0.x; a.y += v0.y; a.z += v0.z; a.w += v0.w;
        b.x += v1.x; b.y += v1.y; b.z += v1.z; b.w += v1.w;
    }
    if (e < end) {
        int s = g_csrc[e];
        float4 v = H[(size_t)s * 64 + f];
        a.x += v.x; a.y += v.y; a.z += v.z; a.w += v.w;
    }
    float nd = g_nd[node], ns = g_ns[node];
    float4 bb = ((const float4*)b1)[f];
    float4 r;
    r.x = fmaxf(fmaf(a.x + b.x, nd, bb.x), 0.f) * ns;
    r.y = fmaxf(fmaf(a.y + b.y, nd, bb.y), 0.f) * ns;
    r.z = fmaxf(fmaf(a.z + b.z, nd, bb.z), 0.f) * ns;
    r.w = fmaxf(fmaf(a.w + b.w, nd, bb.w), 0.f) * ns;
    ((float4*)g_h2s)[(size_t)node * 64 + f] = r;
}

// layer 2: out[node] = sum_{s in in(node)} H2p[s] * nd + b2
__global__ void k_agg2(const float* __restrict__ b2, float* __restrict__ out) {
    int node = blockIdx.x * blockDim.y + threadIdx.y;
    if (node >= NN) return;
    int f = threadIdx.x;  // 0..31 float4 lanes
    const float4* H = (const float4*)g_H2p;
    int beg = g_rowptr[node], end = g_rowptr[node + 1];

    float4 a = make_float4(0.f, 0.f, 0.f, 0.f);
    float4 b = make_float4(0.f, 0.f, 0.f, 0.f);
    int e = beg;
    for (; e + 2 <= end; e += 2) {
        int s0 = g_csrc[e], s1 = g_csrc[e + 1];
        float4 v0 = H[(size_t)s0 * 32 + f];
        float4 v1 = H[(size_t)s1 * 32 + f];
        a.x += v0.x; a.y += v0.y; a.z += v0.z; a.w += v0.w;
        b.x += v1.x; b.y += v1.y; b.z += v1.z; b.w += v1.w;
    }
    if (e < end) {
        int s = g_csrc[e];
        float4 v = H[(size_t)s * 32 + f];
        a.x += v.x; a.y += v.y; a.z += v.z; a.w += v.w;
    }
    float nd = g_nd[node];
    float4 bb = ((const float4*)b2)[f];
    float4 r;
    r.x = fmaf(a.x + b.x, nd, bb.x);
    r.y = fmaf(a.y + b.y, nd, bb.y);
    r.z = fmaf(a.z + b.z, nd, bb.z);
    r.w = fmaf(a.w + b.w, nd, bb.w);
    ((float4*)out)[(size_t)node * 32 + f] = r;
}

// ---------------- launch ----------------
extern "C" void kernel_launch(void* const* d_in, const int* in_sizes, int n_in,
                              void* d_out, int out_size) {
    const float* x   = (const float*)d_in[0];
    const void*  src = d_in[1];
    const void*  dst = d_in[2];
    const float* W1  = (const float*)d_in[3];
    const float* b1  = (const float*)d_in[4];
    const float* W2  = (const float*)d_in[5];
    const float* b2  = (const float*)d_in[6];
    float* out = (float*)d_out;

    k_detect<<<1, 32>>>((const int*)src);
    k_zero<<<(NN + 255) / 256, 256>>>();
    k_degree<<<(NE + 255) / 256, 256>>>(src, dst);
    k_norm<<<(NN + 255) / 256, 256>>>();
    k_scan<<<1, 1024>>>();
    k_csr<<<(NE + 255) / 256, 256>>>(src, dst);

    k_gemm<true><<<dim3((NN + 127) / 128, 2), 256>>>(x, W1);
    k_agg1<<<(NN + 3) / 4, dim3(64, 4)>>>(b1);
    k_gemm<false><<<dim3((NN + 127) / 128, 1), 256>>>(nullptr, W2);
    k_agg2<<<(NN + 7) / 8, dim3(32, 8)>>>(b2, out);
}

// round 4
// speedup vs baseline: 1.0585x; 1.0585x over previous
#include <cuda_runtime.h>

#define NN 50000
#define NE 800000
#define KDIM 256

// ---------------- scratch (static device globals; no allocation) ----------------
__device__ float g_H1[(size_t)NN * 256];    // layer1 projected features
__device__ float g_h2s[(size_t)NN * 256];   // relu(conv1) * norm_src
__device__ float g_H2p[(size_t)NN * 128];   // layer2 projected features
__device__ int   g_deg_out[NN];
__device__ int   g_deg_in[NN];
__device__ float g_ns[NN];                  // norm_src = clip(deg_out,1)^-0.5
__device__ float g_nd[NN];                  // norm_dst = clip(deg_in,1)^-0.5
__device__ int   g_rowptr[NN + 1];
__device__ int   g_cursor[NN];
__device__ int   g_csrc[NE];                // CSR-by-dst: source node ids
__device__ int   g_is64;                    // 1 if src/dst are int64, 0 if int32

// packed dual-FMA: d = a * b + d (2 exact fp32 FMAs per issue slot, sm_100+)
__device__ __forceinline__ void ffma2(float2& d, const float2 a, const float2 b) {
    unsigned long long aa = *reinterpret_cast<const unsigned long long*>(&a);
    unsigned long long bb = *reinterpret_cast<const unsigned long long*>(&b);
    unsigned long long dd = *reinterpret_cast<unsigned long long*>(&d);
    asm("fma.rn.f32x2 %0, %1, %2, %0;" : "+l"(dd) : "l"(aa), "l"(bb));
    d = *reinterpret_cast<float2*>(&dd);
}

// ---------------- edge index accessor (dtype-robust) ----------------
__device__ __forceinline__ int edge_at(const void* p, int i, int is64) {
    if (is64) return (int)((const long long*)p)[i];
    return ((const int*)p)[i];
}

// detect int64 vs int32: int64 node ids < 2^31 have all-zero high words.
__global__ void k_detect(const int* __restrict__ src_as_i32) {
    if (threadIdx.x == 0) {
        int allzero = 1;
        for (int i = 0; i < 256; i++)
            if (src_as_i32[2 * i + 1] != 0) { allzero = 0; break; }
        g_is64 = allzero;
    }
}

// ---------------- graph prep ----------------
__global__ void k_zero() {
    int i = blockIdx.x * 256 + threadIdx.x;
    if (i < NN) { g_deg_out[i] = 0; g_deg_in[i] = 0; g_cursor[i] = 0; }
}

__global__ void k_degree(const void* __restrict__ src,
                         const void* __restrict__ dst) {
    int e = blockIdx.x * 256 + threadIdx.x;
    if (e < NE) {
        int is64 = g_is64;
        unsigned s = (unsigned)edge_at(src, e, is64);
        unsigned d = (unsigned)edge_at(dst, e, is64);
        if (s < NN) atomicAdd(&g_deg_out[s], 1);
        if (d < NN) atomicAdd(&g_deg_in[d], 1);
    }
}

__global__ void k_norm() {
    int i = blockIdx.x * 256 + threadIdx.x;
    if (i < NN) {
        int a = g_deg_out[i]; if (a < 1) a = 1;
        int b = g_deg_in[i];  if (b < 1) b = 1;
        g_ns[i] = rsqrtf((float)a);
        g_nd[i] = rsqrtf((float)b);
    }
}

// single-block exclusive scan of deg_in -> rowptr
__global__ void k_scan() {
    __shared__ int sh[1024];
    const int CH = (NN + 1023) / 1024;  // 49
    int tid = threadIdx.x;
    int st = tid * CH;
    int en = st + CH; if (en > NN) en = NN;
    int s = 0;
    for (int j = st; j < en; ++j) s += g_deg_in[j];
    sh[tid] = s;
    __syncthreads();
    for (int off = 1; off < 1024; off <<= 1) {
        int v = 0;
        if (tid >= off) v = sh[tid - off];
        __syncthreads();
        sh[tid] += v;
        __syncthreads();
    }
    int run = sh[tid] - s;  // exclusive prefix
    for (int j = st; j < en; ++j) { g_rowptr[j] = run; run += g_deg_in[j]; }
    if (tid == 1023) g_rowptr[NN] = sh[1023];
}

__global__ void k_csr(const void* __restrict__ src,
                      const void* __restrict__ dst) {
    int e = blockIdx.x * 256 + threadIdx.x;
    if (e < NE) {
        int is64 = g_is64;
        unsigned s = (unsigned)edge_at(src, e, is64);
        unsigned d = (unsigned)edge_at(dst, e, is64);
        if (s < NN && d < NN) {
            int pos = atomicAdd(&g_cursor[d], 1);
            int slot = g_rowptr[d] + pos;
            if (slot < NE) g_csrc[slot] = (int)s;
        }
    }
}

// ---------------- GEMM: C[M,Nt] = (A .* rowscale) @ B[256,Nt] ----------------
// BM=128, BN=128, BK=16, 256 threads, TM=TN=8, inner loop uses fma.rn.f32x2
template <bool L1>
__global__ void __launch_bounds__(256) k_gemm(const float* __restrict__ Ain,
                                              const float* __restrict__ B) {
    constexpr int Nt = L1 ? 256 : 128;
    const float* A = L1 ? Ain : (const float*)g_h2s;
    float* C = L1 ? g_H1 : g_H2p;

    __shared__ __align__(16) float As[16][128];
    __shared__ __align__(16) float Bs[16][128];

    int brow = blockIdx.x * 128;
    int bcol = blockIdx.y * 128;
    int tid = threadIdx.x;
    int tx = tid & 15;
    int ty = tid >> 4;

    float2 acc[8][4];
#pragma unroll
    for (int i = 0; i < 8; i++)
#pragma unroll
        for (int j = 0; j < 4; j++) acc[i][j] = make_float2(0.f, 0.f);

    for (int k0 = 0; k0 < KDIM; k0 += 16) {
        // load A tile 128x16 (transposed into As[k][m]), scaled by norm_src for layer 1
#pragma unroll
        for (int i = 0; i < 2; i++) {
            int idx = tid * 2 + i;          // 0..511
            int ar = idx >> 2;              // row within tile 0..127
            int ac = (idx & 3) * 4;         // col within tile 0,4,8,12
            int gr = brow + ar;
            float4 v = make_float4(0.f, 0.f, 0.f, 0.f);
            if (gr < NN) {
                v = *(const float4*)(A + (size_t)gr * KDIM + k0 + ac);
                if (L1) {
                    float s = g_ns[gr];
                    v.x *= s; v.y *= s; v.z *= s; v.w *= s;
                }
            }
            As[ac + 0][ar] = v.x;
            As[ac + 1][ar] = v.y;
            As[ac + 2][ar] = v.z;
            As[ac + 3][ar] = v.w;
        }
        // load B tile 16x128
#pragma unroll
        for (int i = 0; i < 2; i++) {
            int idx = tid * 2 + i;
            int br = idx >> 5;              // 0..15
            int bc = (idx & 31) * 4;        // 0..124
            *(float4*)&Bs[br][bc] =
                *(const float4*)(B + (size_t)(k0 + br) * Nt + bcol + bc);
        }
        __syncthreads();

#pragma unroll
        for (int k = 0; k < 16; k++) {
            float4 a0 = *(const float4*)&As[k][ty * 8];
            float4 a1 = *(const float4*)&As[k][ty * 8 + 4];
            float4 b0 = *(const float4*)&Bs[k][tx * 8];
            float4 b1 = *(const float4*)&Bs[k][tx * 8 + 4];
            float ra[8] = {a0.x, a0.y, a0.z, a0.w, a1.x, a1.y, a1.z, a1.w};
            float2 rb[4] = {make_float2(b0.x, b0.y), make_float2(b0.z, b0.w),
                            make_float2(b1.x, b1.y), make_float2(b1.z, b1.w)};
#pragma unroll
            for (int i = 0; i < 8; i++) {
                float2 ad = make_float2(ra[i], ra[i]);
#pragma unroll
                for (int j = 0; j < 4; j++) ffma2(acc[i][j], ad, rb[j]);
            }
        }
        __syncthreads();
    }

#pragma unroll
    for (int i = 0; i < 8; i++) {
        int gr = brow + ty * 8 + i;
        if (gr >= NN) continue;
#pragma unroll
        for (int j = 0; j < 2; j++) {
            float4 v = make_float4(acc[i][2 * j].x, acc[i][2 * j].y,
                                   acc[i][2 * j + 1].x, acc[i][2 * j + 1].y);
            *(float4*)(C + (size_t)gr * Nt + bcol + tx * 8 + 4 * j) = v;
        }
    }
}

// ---------------- aggregation (CSR gather-sum, no float atomics) ----------------
// layer 1: h2s[node] = relu(sum_{s in in(node)} H1[s] * nd + b1) * ns
__global__ void k_agg1(const float* __restrict__ b1) {
    int node = blockIdx.x * blockDim.y + threadIdx.y;
    if (node >= NN) return;
    int f = threadIdx.x;  // 0..63 float4 lanes
    const float4* H = (const float4*)g_H1;
    int beg = g_rowptr[node], end = g_rowptr[node + 1];

    float4 a = make_float4(0.f, 0.f, 0.f, 0.f);
    float4 b = make_float4(0.f, 0.f, 0.f, 0.f);
    int e = beg;
    for (; e + 2 <= end; e += 2) {
        int s0 = g_csrc[e], s1 = g_csrc[e + 1];
        float4 v0 = H[(size_t)s0 * 64 + f];
        float4 v1 = H[(size_t)s1 * 64 + f];
        a.x += v0.x; a.y += v0.y; a.z += v0.z; a.w += v0.w;
        b.x += v1.x; b.y += v1.y; b.z += v1.z; b.w += v1.w;
    }
    if (e < end) {
        int s = g_csrc[e];
        float4 v = H[(size_t)s * 64 + f];
        a.x += v.x; a.y += v.y; a.z += v.z; a.w += v.w;
    }
    float nd = g_nd[node], ns = g_ns[node];
    float4 bb = ((const float4*)b1)[f];
    float4 r;
    r.x = fmaxf(fmaf(a.x + b.x, nd, bb.x), 0.f) * ns;
    r.y = fmaxf(fmaf(a.y + b.y, nd, bb.y), 0.f) * ns;
    r.z = fmaxf(fmaf(a.z + b.z, nd, bb.z), 0.f) * ns;
    r.w = fmaxf(fmaf(a.w + b.w, nd, bb.w), 0.f) * ns;
    ((float4*)g_h2s)[(size_t)node * 64 + f] = r;
}

// layer 2: out[node] = sum_{s in in(node)} H2p[s] * nd + b2
__global__ void k_agg2(const float* __restrict__ b2, float* __restrict__ out) {
    int node = blockIdx.x * blockDim.y + threadIdx.y;
    if (node >= NN) return;
    int f = threadIdx.x;  // 0..31 float4 lanes
    const float4* H = (const float4*)g_H2p;
    int beg = g_rowptr[node], end = g_rowptr[node + 1];

    float4 a = make_float4(0.f, 0.f, 0.f, 0.f);
    float4 b = make_float4(0.f, 0.f, 0.f, 0.f);
    int e = beg;
    for (; e + 2 <= end; e += 2) {
        int s0 = g_csrc[e], s1 = g_csrc[e + 1];
        float4 v0 = H[(size_t)s0 * 32 + f];
        float4 v1 = H[(size_t)s1 * 32 + f];
        a.x += v0.x; a.y += v0.y; a.z += v0.z; a.w += v0.w;
        b.x += v1.x; b.y += v1.y; b.z += v1.z; b.w += v1.w;
    }
    if (e < end) {
        int s = g_csrc[e];
        float4 v = H[(size_t)s * 32 + f];
        a.x += v.x; a.y += v.y; a.z += v.z; a.w += v.w;
    }
    float nd = g_nd[node];
    float4 bb = ((const float4*)b2)[f];
    float4 r;
    r.x = fmaf(a.x + b.x, nd, bb.x);
    r.y = fmaf(a.y + b.y, nd, bb.y);
    r.z = fmaf(a.z + b.z, nd, bb.z);
    r.w = fmaf(a.w + b.w, nd, bb.w);
    ((float4*)out)[(size_t)node * 32 + f] = r;
}

// ---------------- launch ----------------
extern "C" void kernel_launch(void* const* d_in, const int* in_sizes, int n_in,
                              void* d_out, int out_size) {
    const float* x   = (const float*)d_in[0];
    const void*  src = d_in[1];
    const void*  dst = d_in[2];
    const float* W1  = (const float*)d_in[3];
    const float* b1  = (const float*)d_in[4];
    const float* W2  = (const float*)d_in[5];
    const float* b2  = (const float*)d_in[6];
    float* out = (float*)d_out;

    k_detect<<<1, 32>>>((const int*)src);
    k_zero<<<(NN + 255) / 256, 256>>>();
    k_degree<<<(NE + 255) / 256, 256>>>(src, dst);
    k_norm<<<(NN + 255) / 256, 256>>>();
    k_scan<<<1, 1024>>>();
    k_csr<<<(NE + 255) / 256, 256>>>(src, dst);

    k_gemm<true><<<dim3((NN + 127) / 128, 2), 256>>>(x, W1);
    k_agg1<<<(NN + 3) / 4, dim3(64, 4)>>>(b1);
    k_gemm<false><<<dim3((NN + 127) / 128, 1), 256>>>(nullptr, W2);
    k_agg2<<<(NN + 7) / 8, dim3(32, 8)>>>(b2, out);
}

// round 8
// speedup vs baseline: 1.4087x; 1.3308x over previous
#include <cuda_runtime.h>
#include <cuda_bf16.h>
#include <cstdint>

#define NN 50000
#define NE 800000

// ---------------- scratch (static device globals; no allocation) ----------------
__device__ float g_H1[(size_t)NN * 256];    // layer1 projected features
__device__ float g_h2s[(size_t)NN * 256];   // relu(conv1) * norm_src
__device__ float g_H2p[(size_t)NN * 128];   // layer2 projected features
__device__ int   g_deg_out[NN];
__device__ int   g_deg_in[NN];
__device__ float g_ns[NN];
__device__ float g_nd[NN];
__device__ int   g_rowptr[NN + 1];
__device__ int   g_cursor[NN];
__device__ int   g_csrc[NE];
__device__ int   g_is64;

// weight fragment packs: uint2{hi_pair, lo_pair} indexed
// ((ks*NT8 + nt8)*2 + breg)*32 + lane
__device__ uint2 g_B1p[16 * 32 * 2 * 32];   // W1: Nt=256, NT8=32
__device__ uint2 g_B2p[16 * 16 * 2 * 32];   // W2: Nt=128, NT8=16

// bf16 hi/lo split of two fp32, packed as bf16x2
__device__ __forceinline__ uint2 split_pack(float f0, float f1) {
    __nv_bfloat16 h0 = __float2bfloat16(f0), h1 = __float2bfloat16(f1);
    float l0 = f0 - __bfloat162float(h0);
    float l1 = f1 - __bfloat162float(h1);
    __nv_bfloat16 g0 = __float2bfloat16(l0), g1 = __float2bfloat16(l1);
    uint2 r;
    r.x = (uint32_t)__bfloat16_as_ushort(h0) | ((uint32_t)__bfloat16_as_ushort(h1) << 16);
    r.y = (uint32_t)__bfloat16_as_ushort(g0) | ((uint32_t)__bfloat16_as_ushort(g1) << 16);
    return r;
}

__device__ __forceinline__ void mma_bf16(float* c, const uint32_t* a, uint32_t b0, uint32_t b1) {
    asm volatile(
        "mma.sync.aligned.m16n8k16.row.col.f32.bf16.bf16.f32 "
        "{%0,%1,%2,%3}, {%4,%5,%6,%7}, {%8,%9}, {%0,%1,%2,%3};"
        : "+f"(c[0]), "+f"(c[1]), "+f"(c[2]), "+f"(c[3])
        : "r"(a[0]), "r"(a[1]), "r"(a[2]), "r"(a[3]), "r"(b0), "r"(b1));
}

// ---------------- edge index accessor (dtype-robust) ----------------
__device__ __forceinline__ int edge_at(const void* p, int i, int is64) {
    if (is64) return (int)((const long long*)p)[i];
    return ((const int*)p)[i];
}

__global__ void k_detect(const int* __restrict__ src_as_i32) {
    if (threadIdx.x == 0) {
        int allzero = 1;
        for (int i = 0; i < 256; i++)
            if (src_as_i32[2 * i + 1] != 0) { allzero = 0; break; }
        g_is64 = allzero;
    }
}

// ---------------- graph prep ----------------
__global__ void k_zero() {
    int i = blockIdx.x * 256 + threadIdx.x;
    if (i < NN) { g_deg_out[i] = 0; g_deg_in[i] = 0; g_cursor[i] = 0; }
}

__global__ void k_degree(const void* __restrict__ src, const void* __restrict__ dst) {
    int e = blockIdx.x * 256 + threadIdx.x;
    if (e < NE) {
        int is64 = g_is64;
        unsigned s = (unsigned)edge_at(src, e, is64);
        unsigned d = (unsigned)edge_at(dst, e, is64);
        if (s < NN) atomicAdd(&g_deg_out[s], 1);
        if (d < NN) atomicAdd(&g_deg_in[d], 1);
    }
}

__global__ void k_norm() {
    int i = blockIdx.x * 256 + threadIdx.x;
    if (i < NN) {
        int a = g_deg_out[i]; if (a < 1) a = 1;
        int b = g_deg_in[i];  if (b < 1) b = 1;
        g_ns[i] = rsqrtf((float)a);
        g_nd[i] = rsqrtf((float)b);
    }
}

__global__ void k_scan() {
    __shared__ int sh[1024];
    const int CH = (NN + 1023) / 1024;
    int tid = threadIdx.x;
    int st = tid * CH;
    int en = st + CH; if (en > NN) en = NN;
    int s = 0;
    for (int j = st; j < en; ++j) s += g_deg_in[j];
    sh[tid] = s;
    __syncthreads();
    for (int off = 1; off < 1024; off <<= 1) {
        int v = 0;
        if (tid >= off) v = sh[tid - off];
        __syncthreads();
        sh[tid] += v;
        __syncthreads();
    }
    int run = sh[tid] - s;
    for (int j = st; j < en; ++j) { g_rowptr[j] = run; run += g_deg_in[j]; }
    if (tid == 1023) g_rowptr[NN] = sh[1023];
}

__global__ void k_csr(const void* __restrict__ src, const void* __restrict__ dst) {
    int e = blockIdx.x * 256 + threadIdx.x;
    if (e < NE) {
        int is64 = g_is64;
        unsigned s = (unsigned)edge_at(src, e, is64);
        unsigned d = (unsigned)edge_at(dst, e, is64);
        if (s < NN && d < NN) {
            int pos = atomicAdd(&g_cursor[d], 1);
            int slot = g_rowptr[d] + pos;
            if (slot < NE) g_csrc[slot] = (int)s;
        }
    }
}

// ---------------- weight -> fragment-order bf16 hi/lo pack ----------------
// Writes directly to g_B1p / g_B2p (device symbols referenced in device code).
// W is [256, Nt] row-major. b0: k = ks*16 + (lane&3)*2 (+1), n = nt8*8 + lane>>2;
// b1: same with k += 8.
template <bool L1>
__global__ void k_wpack(const float* __restrict__ W) {
    constexpr int Nt = L1 ? 256 : 128;
    constexpr int NT8 = Nt >> 3;
    uint2* out = L1 ? g_B1p : g_B2p;
    int total = 16 * NT8 * 2 * 32;
    int idx = blockIdx.x * 256 + threadIdx.x;
    if (idx >= total) return;
    int lane = idx & 31;
    int breg = (idx >> 5) & 1;
    int rest = idx >> 6;                  // ks*NT8 + nt8
    int nt8 = rest % NT8;
    int ks = rest / NT8;
    int k = ks * 16 + (lane & 3) * 2 + breg * 8;
    int n = nt8 * 8 + (lane >> 2);
    float w0 = W[(size_t)k * Nt + n];
    float w1 = W[(size_t)(k + 1) * Nt + n];
    out[idx] = split_pack(w0, w1);
}

// ---------------- MMA GEMM: C[128 x Nt-tile] = (A .* ns?) @ W, 3x bf16 split ----
// 256 threads = 8 warps (4M x 2N); warp tile 32x64; no shared memory.
template <bool L1>
__global__ void __launch_bounds__(256, 1) k_mma(const float* __restrict__ Ain) {
    constexpr int Nt = L1 ? 256 : 128;
    constexpr int NT8 = Nt >> 3;
    const float* A = L1 ? Ain : (const float*)g_h2s;
    float* C = L1 ? g_H1 : g_H2p;
    const uint2* Bp = L1 ? g_B1p : g_B2p;

    int tid = threadIdx.x;
    int wid = tid >> 5, lid = tid & 31;
    int wm = wid >> 1, wn = wid & 1;
    int g = lid >> 2, q = lid & 3;
    int brow = blockIdx.x * 128;
    int bcol = blockIdx.y * 128;

    int rbase = brow + wm * 32 + g;
    int rows[4] = {rbase, rbase + 8, rbase + 16, rbase + 24};
    float scale[4];
    bool valid[4];
#pragma unroll
    for (int i = 0; i < 4; i++) {
        valid[i] = rows[i] < NN;
        scale[i] = L1 ? (valid[i] ? g_ns[rows[i]] : 0.f) : 1.f;
    }

    float acc[2][8][4];
#pragma unroll
    for (int mt = 0; mt < 2; mt++)
#pragma unroll
        for (int j = 0; j < 8; j++)
#pragma unroll
            for (int c = 0; c < 4; c++) acc[mt][j][c] = 0.f;

    // R7 bug fix: include this block's N-tile offset (bcol>>3) in the B index.
    const uint2* bbase = Bp + (size_t)((bcol >> 3) + wn * 8) * 64 + lid;

    for (int ks = 0; ks < 16; ks++) {
        // ---- A fragments (load fp32, split in registers) ----
        uint32_t ah[2][4], al[2][4];
#pragma unroll
        for (int mt = 0; mt < 2; mt++) {
#pragma unroll
            for (int half = 0; half < 2; half++) {   // row g vs row g+8
                int ri = mt * 2 + half;
                float2 v0 = make_float2(0.f, 0.f), v1 = make_float2(0.f, 0.f);
                if (valid[ri]) {
                    const float* ap = A + (size_t)rows[ri] * 256 + ks * 16 + q * 2;
                    v0 = *(const float2*)ap;          // cols 2q, 2q+1
                    v1 = *(const float2*)(ap + 8);    // cols 2q+8, 2q+9
                    if (L1) {
                        float s = scale[ri];
                        v0.x *= s; v0.y *= s; v1.x *= s; v1.y *= s;
                    }
                }
                uint2 p0 = split_pack(v0.x, v0.y);
                uint2 p1 = split_pack(v1.x, v1.y);
                ah[mt][half] = p0.x;
                al[mt][half] = p0.y;
                ah[mt][half + 2] = p1.x;
                al[mt][half + 2] = p1.y;
            }
        }
        // ---- B fragments (pre-packed, coalesced) ----
        const uint2* bk = bbase + (size_t)ks * NT8 * 64;
        uint2 b0[8], b1[8];
#pragma unroll
        for (int j = 0; j < 8; j++) {
            b0[j] = bk[j * 64];
            b1[j] = bk[j * 64 + 32];
        }
        // ---- MMAs: AhBh + AhBl + AlBh ----
#pragma unroll
        for (int mt = 0; mt < 2; mt++)
#pragma unroll
            for (int j = 0; j < 8; j++) {
                mma_bf16(acc[mt][j], ah[mt], b0[j].x, b1[j].x);
                mma_bf16(acc[mt][j], ah[mt], b0[j].y, b1[j].y);
                mma_bf16(acc[mt][j], al[mt], b0[j].x, b1[j].x);
            }
    }

    // ---- epilogue ----
    int cb = bcol + wn * 64 + q * 2;
#pragma unroll
    for (int mt = 0; mt < 2; mt++) {
        int r0 = rows[mt * 2], r1 = rows[mt * 2 + 1];
#pragma unroll
        for (int j = 0; j < 8; j++) {
            if (valid[mt * 2])
                *(float2*)(C + (size_t)r0 * Nt + cb + j * 8) =
                    make_float2(acc[mt][j][0], acc[mt][j][1]);
            if (valid[mt * 2 + 1])
                *(float2*)(C + (size_t)r1 * Nt + cb + j * 8) =
                    make_float2(acc[mt][j][2], acc[mt][j][3]);
        }
    }
}

// ---------------- aggregation (CSR gather-sum, unroll-4 for MLP) ----------------
__global__ void k_agg1(const float* __restrict__ b1) {
    int node = blockIdx.x * blockDim.y + threadIdx.y;
    if (node >= NN) return;
    int f = threadIdx.x;  // 0..63 float4 lanes
    const float4* H = (const float4*)g_H1;
    int beg = g_rowptr[node], end = g_rowptr[node + 1];

    float4 a = make_float4(0.f, 0.f, 0.f, 0.f);
    float4 b = make_float4(0.f, 0.f, 0.f, 0.f);
    int e = beg;
    for (; e + 4 <= end; e += 4) {
        int s0 = g_csrc[e], s1 = g_csrc[e + 1], s2 = g_csrc[e + 2], s3 = g_csrc[e + 3];
        float4 v0 = H[(size_t)s0 * 64 + f];
        float4 v1 = H[(size_t)s1 * 64 + f];
        float4 v2 = H[(size_t)s2 * 64 + f];
        float4 v3 = H[(size_t)s3 * 64 + f];
        a.x += v0.x; a.y += v0.y; a.z += v0.z; a.w += v0.w;
        b.x += v1.x; b.y += v1.y; b.z += v1.z; b.w += v1.w;
        a.x += v2.x; a.y += v2.y; a.z += v2.z; a.w += v2.w;
        b.x += v3.x; b.y += v3.y; b.z += v3.z; b.w += v3.w;
    }
    for (; e < end; e++) {
        int s = g_csrc[e];
        float4 v = H[(size_t)s * 64 + f];
        a.x += v.x; a.y += v.y; a.z += v.z; a.w += v.w;
    }
    float nd = g_nd[node], ns = g_ns[node];
    float4 bb = ((const float4*)b1)[f];
    float4 r;
    r.x = fmaxf(fmaf(a.x + b.x, nd, bb.x), 0.f) * ns;
    r.y = fmaxf(fmaf(a.y + b.y, nd, bb.y), 0.f) * ns;
    r.z = fmaxf(fmaf(a.z + b.z, nd, bb.z), 0.f) * ns;
    r.w = fmaxf(fmaf(a.w + b.w, nd, bb.w), 0.f) * ns;
    ((float4*)g_h2s)[(size_t)node * 64 + f] = r;
}

__global__ void k_agg2(const float* __restrict__ b2, float* __restrict__ out) {
    int node = blockIdx.x * blockDim.y + threadIdx.y;
    if (node >= NN) return;
    int f = threadIdx.x;  // 0..31 float4 lanes
    const float4* H = (const float4*)g_H2p;
    int beg = g_rowptr[node], end = g_rowptr[node + 1];

    float4 a = make_float4(0.f, 0.f, 0.f, 0.f);
    float4 b = make_float4(0.f, 0.f, 0.f, 0.f);
    int e = beg;
    for (; e + 4 <= end; e += 4) {
        int s0 = g_csrc[e], s1 = g_csrc[e + 1], s2 = g_csrc[e + 2], s3 = g_csrc[e + 3];
        float4 v0 = H[(size_t)s0 * 32 + f];
        float4 v1 = H[(size_t)s1 * 32 + f];
        float4 v2 = H[(size_t)s2 * 32 + f];
        float4 v3 = H[(size_t)s3 * 32 + f];
        a.x += v0.x; a.y += v0.y; a.z += v0.z; a.w += v0.w;
        b.x += v1.x; b.y += v1.y; b.z += v1.z; b.w += v1.w;
        a.x += v2.x; a.y += v2.y; a.z += v2.z; a.w += v2.w;
        b.x += v3.x; b.y += v3.y; b.z += v3.z; b.w += v3.w;
    }
    for (; e < end; e++) {
        int s = g_csrc[e];
        float4 v = H[(size_t)s * 32 + f];
        a.x += v.x; a.y += v.y; a.z += v.z; a.w += v.w;
    }
    float nd = g_nd[node];
    float4 bb = ((const float4*)b2)[f];
    float4 r;
    r.x = fmaf(a.x + b.x, nd, bb.x);
    r.y = fmaf(a.y + b.y, nd, bb.y);
    r.z = fmaf(a.z + b.z, nd, bb.z);
    r.w = fmaf(a.w + b.w, nd, bb.w);
    ((float4*)out)[(size_t)node * 32 + f] = r;
}

// ---------------- launch ----------------
extern "C" void kernel_launch(void* const* d_in, const int* in_sizes, int n_in,
                              void* d_out, int out_size) {
    const float* x   = (const float*)d_in[0];
    const void*  src = d_in[1];
    const void*  dst = d_in[2];
    const float* W1  = (const float*)d_in[3];
    const float* b1  = (const float*)d_in[4];
    const float* W2  = (const float*)d_in[5];
    const float* b2  = (const float*)d_in[6];
    float* out = (float*)d_out;

    k_detect<<<1, 32>>>((const int*)src);
    k_zero<<<(NN + 255) / 256, 256>>>();
    k_degree<<<(NE + 255) / 256, 256>>>(src, dst);
    k_norm<<<(NN + 255) / 256, 256>>>();
    k_scan<<<1, 1024>>>();
    k_csr<<<(NE + 255) / 256, 256>>>(src, dst);
    k_wpack<true><<<128, 256>>>(W1);
    k_wpack<false><<<64, 256>>>(W2);

    const int GB = (NN + 127) / 128;  // 391
    k_mma<true><<<dim3(GB, 2), 256>>>(x);
    k_agg1<<<(NN + 3) / 4, dim3(64, 4)>>>(b1);
    k_mma<false><<<dim3(GB, 1), 256>>>(nullptr);
    k_agg2<<<(NN + 7) / 8, dim3(32, 8)>>>(b2, out);
}